// round 16
// baseline (speedup 1.0000x reference)
#include <cuda_runtime.h>
#include <cuda_bf16.h>
#include <math.h>

#define N_NODES 20000
#define E_EDGES 200000
#define FOUT    256
#define K_IN    768
#define N_SEL   4096

// ---------------- device scratch (static globals: allocation-free) ----------
__device__ float g_ha[(size_t)N_NODES * FOUT];
__device__ float g_hd[(size_t)N_NODES * FOUT];
__device__ float g_oad[(size_t)N_NODES * FOUT];
__device__ float g_odd[(size_t)N_NODES * FOUT];
__device__ float g_as_ad[N_NODES * 2];
__device__ float g_ad_ad[N_NODES * 2];
__device__ float g_as_dd[N_NODES * 2];
__device__ float g_ad_dd[N_NODES * 2];
__device__ float g_w_ad[E_EDGES * 2];
__device__ float g_w_dd[E_EDGES * 2];
__device__ float g_s_ad[N_NODES * 2];
__device__ float g_s_dd[N_NODES * 2];
__device__ float g_score[2];
// CSR scratch
__device__ int g_deg0[N_NODES];
__device__ int g_deg1[N_NODES];
__device__ int g_start0[N_NODES];
__device__ int g_start1[N_NODES];
__device__ int g_cur0[N_NODES];
__device__ int g_cur1[N_NODES];
__device__ int g_csr0[E_EDGES];
__device__ int g_csr1[E_EDGES];
// bf16-split mirrors (hi/mid) of the WEIGHTS only (small, split once)
__device__ __nv_bfloat16 g_wh0[FOUT * K_IN];
__device__ __nv_bfloat16 g_wm0[FOUT * K_IN];
__device__ __nv_bfloat16 g_wh1[FOUT * K_IN];
__device__ __nv_bfloat16 g_wm1[FOUT * K_IN];
__device__ __nv_bfloat16 g_kwh[FOUT * FOUT];
__device__ __nv_bfloat16 g_kwm[FOUT * FOUT];

// ---------------- helpers ---------------------------------------------------
__device__ __forceinline__ float dot4(float4 a, float4 b) {
    return a.x * b.x + a.y * b.y + a.z * b.z + a.w * b.w;
}

__device__ __forceinline__ float warp_sum(float v) {
#pragma unroll
    for (int o = 16; o > 0; o >>= 1) v += __shfl_xor_sync(0xffffffffu, v, o);
    return v;
}

// bf16 two-component split: x ~= hi + mid, error O(2^-18 * x)
__device__ __forceinline__ void bsplit(float x, __nv_bfloat16& h, __nv_bfloat16& m) {
    h = __float2bfloat16_rn(x);
    m = __float2bfloat16_rn(x - __bfloat162float(h));
}

// m16n8k16 bf16 MMA, fp32 accumulate
__device__ __forceinline__ void mma_bf16(float* c, const unsigned* a, const unsigned* b) {
    asm volatile(
        "mma.sync.aligned.m16n8k16.row.col.f32.bf16.bf16.f32 "
        "{%0,%1,%2,%3}, {%4,%5,%6,%7}, {%8,%9}, {%0,%1,%2,%3};"
        : "+f"(c[0]), "+f"(c[1]), "+f"(c[2]), "+f"(c[3])
        : "r"(a[0]), "r"(a[1]), "r"(a[2]), "r"(a[3]), "r"(b[0]), "r"(b[1]));
}

__device__ __forceinline__ void cp_async16(void* sdst, const void* gsrc) {
    unsigned s = (unsigned)__cvta_generic_to_shared(sdst);
    asm volatile("cp.async.cg.shared.global [%0], [%1], 16;" :: "r"(s), "l"(gsrc)
                 : "memory");
}

#define SA 40                  // bf16 row stride: conflict-free fragment loads
#define A_TILE (128 * SA)      // Ah/Am bf16 elems (single-buffered)
#define B_TILE (256 * SA)      // Bh/Bm bf16 elems per stage (double-buffered)
// smem: fp32 A staging (double) + Ah/Am (single) + Bh/Bm (double)
#define GEMM_SMEM_BYTES (2*4096*4 + 2*A_TILE*2 + 4*B_TILE*2)   // 135168

// ---------------- kernel 0: fp32 -> bf16 hi/mid split (weights only) --------
__global__ __launch_bounds__(256) void split_kernel(
    const float* __restrict__ s0, __nv_bfloat16* __restrict__ h0,
    __nv_bfloat16* __restrict__ m0,
    const float* __restrict__ s1, __nv_bfloat16* __restrict__ h1,
    __nv_bfloat16* __restrict__ m1, int n4)
{
    const float* s = blockIdx.y ? s1 : s0;
    __nv_bfloat16* h = blockIdx.y ? h1 : h0;
    __nv_bfloat16* m = blockIdx.y ? m1 : m0;
    int i = blockIdx.x * 256 + threadIdx.x;
    if (i >= n4) return;
    float4 v = ((const float4*)s)[i];
    __nv_bfloat16 h0v, m0v, h1v, m1v, h2v, m2v, h3v, m3v;
    bsplit(v.x, h0v, m0v); bsplit(v.y, h1v, m1v);
    bsplit(v.z, h2v, m2v); bsplit(v.w, h3v, m3v);
    union { __nv_bfloat162 b[2]; uint2 u; } ph, pm;
    ph.b[0] = __nv_bfloat162(h0v, h1v); ph.b[1] = __nv_bfloat162(h2v, h3v);
    pm.b[0] = __nv_bfloat162(m0v, m1v); pm.b[1] = __nv_bfloat162(m2v, m3v);
    ((uint2*)h)[i] = ph.u;
    ((uint2*)m)[i] = pm.u;
}

// ---------------- kernel 1: h = x @ W^T + b  --------------------------------
// Tile 128(M) x 256(N = full FOUT), 512 threads. A staged fp32 + split
// in-kernel ONCE per element (grid.x = 1). W arrives pre-split bf16 via
// cp.async directly into the mma tiles (no convert). K-chunk 32.
__global__ void __launch_bounds__(512, 1) mma_gemm_bias_kernel(
    const float* __restrict__ A0,
    const __nv_bfloat16* __restrict__ Wh0, const __nv_bfloat16* __restrict__ Wm0,
    const float* __restrict__ bias0, float* __restrict__ C0,
    const float* __restrict__ A1,
    const __nv_bfloat16* __restrict__ Wh1, const __nv_bfloat16* __restrict__ Wm1,
    const float* __restrict__ bias1, float* __restrict__ C1,
    int M, int K)
{
    extern __shared__ __align__(16) char dynsmem[];
    float* SAf = (float*)dynsmem;                                 // [2][4096]
    __nv_bfloat16* Ah = (__nv_bfloat16*)(SAf + 2 * 4096);         // [A_TILE]
    __nv_bfloat16* Am = Ah + A_TILE;                              // [A_TILE]
    __nv_bfloat16* Bh = Am + A_TILE;                              // [2][B_TILE]
    __nv_bfloat16* Bm = Bh + 2 * B_TILE;                          // [2][B_TILE]

    const float* A = blockIdx.z ? A1 : A0;
    const __nv_bfloat16* Whg = blockIdx.z ? Wh1 : Wh0;
    const __nv_bfloat16* Wmg = blockIdx.z ? Wm1 : Wm0;
    const float* bias = blockIdx.z ? bias1 : bias0;
    float*       C    = blockIdx.z ? C1 : C0;

    const int tid = threadIdx.x;
    const int lane = tid & 31;
    const int wid = tid >> 5;           // 0..15
    const int warp_m = wid & 3;         // 4 warps over M (32 rows each)
    const int warp_n = wid >> 2;        // 4 warps over N (64 cols each)
    const int rowBase = blockIdx.y * 128;

    float acc[2][8][4];
#pragma unroll
    for (int mt = 0; mt < 2; mt++)
#pragma unroll
        for (int nt = 0; nt < 8; nt++)
#pragma unroll
            for (int i = 0; i < 4; i++) acc[mt][nt][i] = 0.f;

    const int lrow = lane >> 2;
    const int lk = (lane & 3) * 2;

    auto issue_chunk = [&](int k0, int buf) {
        // A: 128 rows x 32 k fp32 = 1024 x 16B, 2 per thread
#pragma unroll
        for (int i = 0; i < 2; i++) {
            int idx = tid + i * 512;
            int row = idx >> 3;           // 0..127
            int f4 = idx & 7;             // 0..7 (4 floats each)
            int grow = rowBase + row; if (grow > M - 1) grow = M - 1;
            cp_async16(SAf + buf * 4096 + idx * 4, A + (size_t)grow * K + k0 + f4 * 4);
        }
        // Bh / Bm: 256 rows x 32 k bf16 = 1024 x 16B each, 2+2 per thread
#pragma unroll
        for (int i = 0; i < 2; i++) {
            int idx = tid + i * 512;
            int row = idx >> 2;           // 0..255
            int f4 = idx & 3;             // 0..3 (8 bf16 each)
            cp_async16(Bh + buf * B_TILE + row * SA + f4 * 8,
                       Whg + (size_t)row * K + k0 + f4 * 8);
            cp_async16(Bm + buf * B_TILE + row * SA + f4 * 8,
                       Wmg + (size_t)row * K + k0 + f4 * 8);
        }
        asm volatile("cp.async.commit_group;" ::: "memory");
    };

    const int nChunks = K / 32;
    issue_chunk(0, 0);

    for (int kc = 0; kc < nChunks; kc++) {
        const int buf = kc & 1;
        if (kc + 1 < nChunks) {
            issue_chunk((kc + 1) * 32, buf ^ 1);
            asm volatile("cp.async.wait_group 1;" ::: "memory");
        } else {
            asm volatile("cp.async.wait_group 0;" ::: "memory");
        }
        // convert own A slots fp32 -> bf16 hi/mid (prev mma done: trailing bar)
#pragma unroll
        for (int i = 0; i < 2; i++) {
            int idx = tid + i * 512;
            int row = idx >> 3;
            int f4 = idx & 7;
            float4 v = ((const float4*)(SAf + buf * 4096))[idx];
            __nv_bfloat16 h0, m0, h1, m1, h2, m2, h3, m3;
            bsplit(v.x, h0, m0); bsplit(v.y, h1, m1);
            bsplit(v.z, h2, m2); bsplit(v.w, h3, m3);
            int o = row * SA + f4 * 4;
            *(__nv_bfloat162*)&Ah[o]     = __nv_bfloat162(h0, h1);
            *(__nv_bfloat162*)&Ah[o + 2] = __nv_bfloat162(h2, h3);
            *(__nv_bfloat162*)&Am[o]     = __nv_bfloat162(m0, m1);
            *(__nv_bfloat162*)&Am[o + 2] = __nv_bfloat162(m2, m3);
        }
        __syncthreads();
        const __nv_bfloat16* BhS = Bh + buf * B_TILE;
        const __nv_bfloat16* BmS = Bm + buf * B_TILE;

#pragma unroll
        for (int kk = 0; kk < 2; kk++) {
            const int kb = kk * 16;
            unsigned ah[2][4], am[2][4];
#pragma unroll
            for (int mt = 0; mt < 2; mt++) {
                int r0 = (warp_m * 32 + mt * 16 + lrow) * SA + kb + lk;
                ah[mt][0] = *(const unsigned*)&Ah[r0];
                ah[mt][1] = *(const unsigned*)&Ah[r0 + 8 * SA];
                ah[mt][2] = *(const unsigned*)&Ah[r0 + 8];
                ah[mt][3] = *(const unsigned*)&Ah[r0 + 8 * SA + 8];
                am[mt][0] = *(const unsigned*)&Am[r0];
                am[mt][1] = *(const unsigned*)&Am[r0 + 8 * SA];
                am[mt][2] = *(const unsigned*)&Am[r0 + 8];
                am[mt][3] = *(const unsigned*)&Am[r0 + 8 * SA + 8];
            }
#pragma unroll
            for (int nt = 0; nt < 8; nt++) {
                int n0 = (warp_n * 64 + nt * 8 + lrow) * SA + kb + lk;
                unsigned bh[2], bm[2];
                bh[0] = *(const unsigned*)&BhS[n0];
                bh[1] = *(const unsigned*)&BhS[n0 + 8];
                bm[0] = *(const unsigned*)&BmS[n0];
                bm[1] = *(const unsigned*)&BmS[n0 + 8];
#pragma unroll
                for (int mt = 0; mt < 2; mt++) {
                    mma_bf16(acc[mt][nt], ah[mt], bh);
                    mma_bf16(acc[mt][nt], ah[mt], bm);
                    mma_bf16(acc[mt][nt], am[mt], bh);
                }
            }
        }
        __syncthreads();
    }

#pragma unroll
    for (int mt = 0; mt < 2; mt++) {
        int r = rowBase + warp_m * 32 + mt * 16 + lrow;
#pragma unroll
        for (int nt = 0; nt < 8; nt++) {
            int c = warp_n * 64 + nt * 8 + lk;
            float b0 = bias[c], b1 = bias[c + 1];
            if (r < M) {
                float2 o = make_float2(acc[mt][nt][0] + b0, acc[mt][nt][1] + b1);
                *(float2*)&C[(size_t)r * FOUT + c] = o;
            }
            if (r + 8 < M) {
                float2 o = make_float2(acc[mt][nt][2] + b0, acc[mt][nt][3] + b1);
                *(float2*)&C[(size_t)(r + 8) * FOUT + c] = o;
            }
        }
    }
}

// ---------------- kernel 2: per-node attention dot products -----------------
__global__ __launch_bounds__(256) void dots_kernel(
    const float* __restrict__ ha, const float* __restrict__ hd,
    const float* __restrict__ att_ad_s, const float* __restrict__ att_ad_d,
    const float* __restrict__ att_dd_s, const float* __restrict__ att_dd_d,
    float* __restrict__ as_ad, float* __restrict__ ad_ad,
    float* __restrict__ as_dd, float* __restrict__ ad_dd, int N)
{
    int warp = (blockIdx.x * blockDim.x + threadIdx.x) >> 5;
    int lane = threadIdx.x & 31;
    if (warp >= N) return;
    const float4* ha4 = (const float4*)(ha + (size_t)warp * FOUT);
    const float4* hd4 = (const float4*)(hd + (size_t)warp * FOUT);
    float4 a0 = ha4[lane], a1 = ha4[32 + lane];
    float4 d0 = hd4[lane], d1 = hd4[32 + lane];

    const float4* v;
    float r;
    v = (const float4*)att_ad_s;
    r = warp_sum(dot4(a0, v[lane]));          if (lane == 0) as_ad[2 * warp + 0] = r;
    r = warp_sum(dot4(a1, v[32 + lane]));     if (lane == 0) as_ad[2 * warp + 1] = r;
    v = (const float4*)att_ad_d;
    r = warp_sum(dot4(d0, v[lane]));          if (lane == 0) ad_ad[2 * warp + 0] = r;
    r = warp_sum(dot4(d1, v[32 + lane]));     if (lane == 0) ad_ad[2 * warp + 1] = r;
    v = (const float4*)att_dd_s;
    r = warp_sum(dot4(d0, v[lane]));          if (lane == 0) as_dd[2 * warp + 0] = r;
    r = warp_sum(dot4(d1, v[32 + lane]));     if (lane == 0) as_dd[2 * warp + 1] = r;
    v = (const float4*)att_dd_d;
    r = warp_sum(dot4(d0, v[lane]));          if (lane == 0) ad_dd[2 * warp + 0] = r;
    r = warp_sum(dot4(d1, v[32 + lane]));     if (lane == 0) ad_dd[2 * warp + 1] = r;
}

// ---------------- kernel 3: edge weights + denominators ---------------------
__global__ __launch_bounds__(256) void edge_w_kernel(
    const int* __restrict__ ei0, const float* __restrict__ as0,
    const float* __restrict__ ad0, float* __restrict__ w0, float* __restrict__ s0,
    const int* __restrict__ ei1, const float* __restrict__ as1,
    const float* __restrict__ ad1, float* __restrict__ w1, float* __restrict__ s1,
    int E)
{
    const int* ei = blockIdx.y ? ei1 : ei0;
    const float* asrc = blockIdx.y ? as1 : as0;
    const float* adst = blockIdx.y ? ad1 : ad0;
    float* w = blockIdx.y ? w1 : w0;
    float* s = blockIdx.y ? s1 : s0;
    int e = blockIdx.x * blockDim.x + threadIdx.x;
    if (e >= E) return;
    int src = ei[e];
    int dst = ei[E + e];
#pragma unroll
    for (int h = 0; h < 2; h++) {
        float v = asrc[2 * src + h] + adst[2 * dst + h];
        v = v > 0.f ? v : 0.2f * v;
        float we = expf(v);
        w[2 * e + h] = we;
        atomicAdd(&s[2 * dst + h], we);
    }
}

// ---------------- CSR build (stream B, input-only dependencies) -------------
__global__ __launch_bounds__(256) void deg_kernel(
    const int* __restrict__ ei0, int* __restrict__ d0,
    const int* __restrict__ ei1, int* __restrict__ d1, int E)
{
    const int* ei = blockIdx.y ? ei1 : ei0;
    int* deg = blockIdx.y ? d1 : d0;
    int e = blockIdx.x * blockDim.x + threadIdx.x;
    if (e < E) atomicAdd(&deg[ei[E + e]], 1);
}

// exclusive scan of degrees — shfl-based 3-level, 2 barriers total
__global__ __launch_bounds__(1024) void scan_kernel(
    const int* __restrict__ deg0, int* __restrict__ start0, int* __restrict__ cur0,
    const int* __restrict__ deg1, int* __restrict__ start1, int* __restrict__ cur1)
{
    const int* deg = blockIdx.x ? deg1 : deg0;
    int* start = blockIdx.x ? start1 : start0;
    int* cur   = blockIdx.x ? cur1 : cur0;
    __shared__ int wsum[32];
    const int t = threadIdx.x;
    const int lane = t & 31;
    const int w = t >> 5;
    const int base = t * 20;
    int vals[20];
    int local = 0;
#pragma unroll
    for (int i = 0; i < 20; i++) {
        int idx = base + i;
        vals[i] = (idx < N_NODES) ? deg[idx] : 0;
        local += vals[i];
    }
    int inc = local;
#pragma unroll
    for (int o = 1; o < 32; o <<= 1) {
        int v = __shfl_up_sync(0xffffffffu, inc, o);
        if (lane >= o) inc += v;
    }
    if (lane == 31) wsum[w] = inc;
    __syncthreads();
    if (w == 0) {
        int v = wsum[lane];
        int inc2 = v;
#pragma unroll
        for (int o = 1; o < 32; o <<= 1) {
            int u = __shfl_up_sync(0xffffffffu, inc2, o);
            if (lane >= o) inc2 += u;
        }
        wsum[lane] = inc2 - v;
    }
    __syncthreads();
    int run = wsum[w] + inc - local;
#pragma unroll
    for (int i = 0; i < 20; i++) {
        int idx = base + i;
        if (idx < N_NODES) {
            start[idx] = run;
            cur[idx] = run;
            run += vals[i];
        }
    }
}

__global__ __launch_bounds__(256) void fill_kernel(
    const int* __restrict__ ei0, int* __restrict__ cur0, int* __restrict__ csr0,
    const int* __restrict__ ei1, int* __restrict__ cur1, int* __restrict__ csr1,
    int E)
{
    const int* ei = blockIdx.y ? ei1 : ei0;
    int* cur = blockIdx.y ? cur1 : cur0;
    int* csr = blockIdx.y ? csr1 : csr0;
    int e = blockIdx.x * blockDim.x + threadIdx.x;
    if (e >= E) return;
    int dst = ei[E + e];
    int pos = atomicAdd(&cur[dst], 1);
    csr[pos] = e;
}

// ---------------- kernel 4: gather (warp per node, window-batched indices) --
__global__ __launch_bounds__(256) void gather_kernel(
    const int* __restrict__ ei0, const int* __restrict__ csr0,
    const int* __restrict__ start0, const int* __restrict__ end0,
    const float* __restrict__ w0, const float* __restrict__ s0,
    const float* __restrict__ h0, float* __restrict__ o0,
    const int* __restrict__ ei1, const int* __restrict__ csr1,
    const int* __restrict__ start1, const int* __restrict__ end1,
    const float* __restrict__ w1, const float* __restrict__ s1,
    const float* __restrict__ h1, float* __restrict__ o1,
    int N)
{
    const int* ei    = blockIdx.y ? ei1 : ei0;
    const int* csr   = blockIdx.y ? csr1 : csr0;
    const int* start = blockIdx.y ? start1 : start0;
    const int* end   = blockIdx.y ? end1 : end0;
    const float* w   = blockIdx.y ? w1 : w0;
    const float* s   = blockIdx.y ? s1 : s0;
    const float* h   = blockIdx.y ? h1 : h0;
    float* out       = blockIdx.y ? o1 : o0;

    int gw = (blockIdx.x * blockDim.x + threadIdx.x) >> 5;
    int lane = threadIdx.x & 31;
    if (gw >= N) return;
    int st = start[gw], en = end[gw];
    float4 a0 = make_float4(0.f, 0.f, 0.f, 0.f);
    float4 a1 = make_float4(0.f, 0.f, 0.f, 0.f);
    for (int wst = st; wst < en; wst += 32) {
        int j = wst + lane;
        int srcv = 0;
        float2 wv = make_float2(0.f, 0.f);
        if (j < en) {
            int e = csr[j];
            srcv = ei[e];
            wv = ((const float2*)w)[e];
        }
        int cnt = en - wst; if (cnt > 32) cnt = 32;
        for (int t = 0; t < cnt; t++) {
            int src = __shfl_sync(0xffffffffu, srcv, t);
            float we0 = __shfl_sync(0xffffffffu, wv.x, t);
            float we1 = __shfl_sync(0xffffffffu, wv.y, t);
            const float4* h4 = (const float4*)(h + (size_t)src * FOUT);
            float4 v0 = h4[lane];
            float4 v1 = h4[32 + lane];
            a0.x += we0 * v0.x; a0.y += we0 * v0.y;
            a0.z += we0 * v0.z; a0.w += we0 * v0.w;
            a1.x += we1 * v1.x; a1.y += we1 * v1.y;
            a1.z += we1 * v1.z; a1.w += we1 * v1.w;
        }
    }
    float is0 = 1.f / (s[2 * gw + 0] + 1e-16f);
    float is1 = 1.f / (s[2 * gw + 1] + 1e-16f);
    float4 r0 = make_float4(fmaxf(a0.x * is0, 0.f), fmaxf(a0.y * is0, 0.f),
                            fmaxf(a0.z * is0, 0.f), fmaxf(a0.w * is0, 0.f));
    float4 r1 = make_float4(fmaxf(a1.x * is1, 0.f), fmaxf(a1.y * is1, 0.f),
                            fmaxf(a1.z * is1, 0.f), fmaxf(a1.w * is1, 0.f));
    float* o = out + (size_t)gw * FOUT;
    ((float4*)o)[lane] = r0;
    ((float4*)o)[32 + lane] = r1;
}

// ---------------- kernel 5: semantic attention score ------------------------
// Same 512-thread / 128x256-tile structure; A = oad/odd (fp32, relu+split
// in-kernel), B = pre-split kW. K = 256.
__global__ void __launch_bounds__(512, 1) sem_mma_kernel(
    const float* __restrict__ A0, const float* __restrict__ A1,
    const __nv_bfloat16* __restrict__ kWh, const __nv_bfloat16* __restrict__ kWm,
    const float* __restrict__ kb, const float* __restrict__ q,
    float* __restrict__ score, int M)
{
    extern __shared__ __align__(16) char dynsmem[];
    float* SAf = (float*)dynsmem;
    __nv_bfloat16* Ah = (__nv_bfloat16*)(SAf + 2 * 4096);
    __nv_bfloat16* Am = Ah + A_TILE;
    __nv_bfloat16* Bh = Am + A_TILE;
    __nv_bfloat16* Bm = Bh + 2 * B_TILE;
    __shared__ float sred[512];

    const float* A = blockIdx.z ? A1 : A0;
    const int K = FOUT;   // 256
    const int tid = threadIdx.x;
    const int lane = tid & 31;
    const int wid = tid >> 5;
    const int warp_m = wid & 3;
    const int warp_n = wid >> 2;
    const int rowBase = blockIdx.y * 128;

    float acc[2][8][4];
#pragma unroll
    for (int mt = 0; mt < 2; mt++)
#pragma unroll
        for (int nt = 0; nt < 8; nt++)
#pragma unroll
            for (int i = 0; i < 4; i++) acc[mt][nt][i] = 0.f;

    const int lrow = lane >> 2;
    const int lk = (lane & 3) * 2;

    auto issue_chunk = [&](int k0, int buf) {
#pragma unroll
        for (int i = 0; i < 2; i++) {
            int idx = tid + i * 512;
            int row = idx >> 3;
            int f4 = idx & 7;
            int grow = rowBase + row; if (grow > M - 1) grow = M - 1;
            cp_async16(SAf + buf * 4096 + idx * 4, A + (size_t)grow * K + k0 + f4 * 4);
        }
#pragma unroll
        for (int i = 0; i < 2; i++) {
            int idx = tid + i * 512;
            int row = idx >> 2;
            int f4 = idx & 3;
            cp_async16(Bh + buf * B_TILE + row * SA + f4 * 8,
                       kWh + (size_t)row * K + k0 + f4 * 8);
            cp_async16(Bm + buf * B_TILE + row * SA + f4 * 8,
                       kWm + (size_t)row * K + k0 + f4 * 8);
        }
        asm volatile("cp.async.commit_group;" ::: "memory");
    };

    const int nChunks = K / 32;   // 8
    issue_chunk(0, 0);

    for (int kc = 0; kc < nChunks; kc++) {
        const int buf = kc & 1;
        if (kc + 1 < nChunks) {
            issue_chunk((kc + 1) * 32, buf ^ 1);
            asm volatile("cp.async.wait_group 1;" ::: "memory");
        } else {
            asm volatile("cp.async.wait_group 0;" ::: "memory");
        }
#pragma unroll
        for (int i = 0; i < 2; i++) {
            int idx = tid + i * 512;
            int row = idx >> 3;
            int f4 = idx & 7;
            float4 v = ((const float4*)(SAf + buf * 4096))[idx];
            v.x = fmaxf(v.x, 0.f); v.y = fmaxf(v.y, 0.f);   // relu (idempotent)
            v.z = fmaxf(v.z, 0.f); v.w = fmaxf(v.w, 0.f);
            __nv_bfloat16 h0, m0, h1, m1, h2, m2, h3, m3;
            bsplit(v.x, h0, m0); bsplit(v.y, h1, m1);
            bsplit(v.z, h2, m2); bsplit(v.w, h3, m3);
            int o = row * SA + f4 * 4;
            *(__nv_bfloat162*)&Ah[o]     = __nv_bfloat162(h0, h1);
            *(__nv_bfloat162*)&Ah[o + 2] = __nv_bfloat162(h2, h3);
            *(__nv_bfloat162*)&Am[o]     = __nv_bfloat162(m0, m1);
            *(__nv_bfloat162*)&Am[o + 2] = __nv_bfloat162(m2, m3);
        }
        __syncthreads();
        const __nv_bfloat16* BhS = Bh + buf * B_TILE;
        const __nv_bfloat16* BmS = Bm + buf * B_TILE;

#pragma unroll
        for (int kk = 0; kk < 2; kk++) {
            const int kb2 = kk * 16;
            unsigned ah[2][4], am[2][4];
#pragma unroll
            for (int mt = 0; mt < 2; mt++) {
                int r0 = (warp_m * 32 + mt * 16 + lrow) * SA + kb2 + lk;
                ah[mt][0] = *(const unsigned*)&Ah[r0];
                ah[mt][1] = *(const unsigned*)&Ah[r0 + 8 * SA];
                ah[mt][2] = *(const unsigned*)&Ah[r0 + 8];
                ah[mt][3] = *(const unsigned*)&Ah[r0 + 8 * SA + 8];
                am[mt][0] = *(const unsigned*)&Am[r0];
                am[mt][1] = *(const unsigned*)&Am[r0 + 8 * SA];
                am[mt][2] = *(const unsigned*)&Am[r0 + 8];
                am[mt][3] = *(const unsigned*)&Am[r0 + 8 * SA + 8];
            }
#pragma unroll
            for (int nt = 0; nt < 8; nt++) {
                int n0 = (warp_n * 64 + nt * 8 + lrow) * SA + kb2 + lk;
                unsigned bh[2], bm[2];
                bh[0] = *(const unsigned*)&BhS[n0];
                bh[1] = *(const unsigned*)&BhS[n0 + 8];
                bm[0] = *(const unsigned*)&BmS[n0];
                bm[1] = *(const unsigned*)&BmS[n0 + 8];
#pragma unroll
                for (int mt = 0; mt < 2; mt++) {
                    mma_bf16(acc[mt][nt], ah[mt], bh);
                    mma_bf16(acc[mt][nt], ah[mt], bm);
                    mma_bf16(acc[mt][nt], am[mt], bh);
                }
            }
        }
        __syncthreads();
    }

    float local = 0.f;
#pragma unroll
    for (int mt = 0; mt < 2; mt++) {
        int r = rowBase + warp_m * 32 + mt * 16 + lrow;
#pragma unroll
        for (int nt = 0; nt < 8; nt++) {
            int c = warp_n * 64 + nt * 8 + lk;
            float kb0 = kb[c], kb1 = kb[c + 1];
            float q0 = q[c], q1 = q[c + 1];
            if (r < M)
                local += tanhf(acc[mt][nt][0] + kb0) * q0 + tanhf(acc[mt][nt][1] + kb1) * q1;
            if (r + 8 < M)
                local += tanhf(acc[mt][nt][2] + kb0) * q0 + tanhf(acc[mt][nt][3] + kb1) * q1;
        }
    }
    sred[tid] = local;
    __syncthreads();
#pragma unroll
    for (int st = 256; st > 0; st >>= 1) {
        if (tid < st) sred[tid] += sred[tid + st];
        __syncthreads();
    }
    if (tid == 0) atomicAdd(&score[blockIdx.z], sred[0] * (1.0f / (float)N_NODES));
}

// ---------------- kernel 6: 2-way softmax + gather --------------------------
__global__ __launch_bounds__(256) void final_kernel(
    const int* __restrict__ idx,
    const float* __restrict__ oa, const float* __restrict__ od,
    const float* __restrict__ score, float* __restrict__ out)
{
    int t = blockIdx.x * blockDim.x + threadIdx.x;
    if (t >= N_SEL * 64) return;
    float s0 = score[0], s1 = score[1];
    float m = fmaxf(s0, s1);
    float e0 = expf(s0 - m), e1 = expf(s1 - m);
    float inv = 1.f / (e0 + e1);
    float a0 = e0 * inv, a1 = e1 * inv;
    int sel = t >> 6, c4 = t & 63;
    int row = idx[sel];
    float4 u = ((const float4*)(oa + (size_t)row * FOUT))[c4];
    float4 v = ((const float4*)(od + (size_t)row * FOUT))[c4];
    float4 r;
    r.x = a0 * fmaxf(u.x, 0.f) + a1 * fmaxf(v.x, 0.f);
    r.y = a0 * fmaxf(u.y, 0.f) + a1 * fmaxf(v.y, 0.f);
    r.z = a0 * fmaxf(u.z, 0.f) + a1 * fmaxf(v.z, 0.f);
    r.w = a0 * fmaxf(u.w, 0.f) + a1 * fmaxf(v.w, 0.f);
    ((float4*)out)[t] = r;
}

// ---------------- launch ----------------------------------------------------
extern "C" void kernel_launch(void* const* d_in, const int* in_sizes, int n_in,
                              void* d_out, int out_size)
{
    (void)in_sizes; (void)n_in; (void)out_size;
    const float* x_add    = (const float*)d_in[0];
    const float* x_del    = (const float*)d_in[1];
    const float* W_add    = (const float*)d_in[2];
    const float* b_add    = (const float*)d_in[3];
    const float* W_del    = (const float*)d_in[4];
    const float* b_del    = (const float*)d_in[5];
    const float* att_ad_s = (const float*)d_in[6];
    const float* att_ad_d = (const float*)d_in[7];
    // d_in[8..11] = att_da_*/att_aa_* — metapaths feed a discarded output: skipped
    const float* att_dd_s = (const float*)d_in[12];
    const float* att_dd_d = (const float*)d_in[13];
    const float* k_W      = (const float*)d_in[14];
    const float* k_b      = (const float*)d_in[15];
    const float* q        = (const float*)d_in[16];
    const int*   ei_ad    = (const int*)d_in[17];
    // d_in[18], d_in[19] = ei_da, ei_aa: skipped
    const int*   ei_dd    = (const int*)d_in[20];
    const int*   del_idx  = (const int*)d_in[21];

    float *ha, *hd, *oad, *odd, *asad, *adad, *asdd, *addd, *wad, *wdd, *sad, *sdd, *score;
    int *deg0, *deg1, *start0, *start1, *cur0, *cur1, *csr0, *csr1;
    __nv_bfloat16 *wh0, *wm0, *wh1, *wm1, *kwh, *kwm;
    cudaGetSymbolAddress((void**)&ha,    g_ha);
    cudaGetSymbolAddress((void**)&hd,    g_hd);
    cudaGetSymbolAddress((void**)&oad,   g_oad);
    cudaGetSymbolAddress((void**)&odd,   g_odd);
    cudaGetSymbolAddress((void**)&asad,  g_as_ad);
    cudaGetSymbolAddress((void**)&adad,  g_ad_ad);
    cudaGetSymbolAddress((void**)&asdd,  g_as_dd);
    cudaGetSymbolAddress((void**)&addd,  g_ad_dd);
    cudaGetSymbolAddress((void**)&wad,   g_w_ad);
    cudaGetSymbolAddress((void**)&wdd,   g_w_dd);
    cudaGetSymbolAddress((void**)&sad,   g_s_ad);
    cudaGetSymbolAddress((void**)&sdd,   g_s_dd);
    cudaGetSymbolAddress((void**)&score, g_score);
    cudaGetSymbolAddress((void**)&deg0,  g_deg0);
    cudaGetSymbolAddress((void**)&deg1,  g_deg1);
    cudaGetSymbolAddress((void**)&start0, g_start0);
    cudaGetSymbolAddress((void**)&start1, g_start1);
    cudaGetSymbolAddress((void**)&cur0,  g_cur0);
    cudaGetSymbolAddress((void**)&cur1,  g_cur1);
    cudaGetSymbolAddress((void**)&csr0,  g_csr0);
    cudaGetSymbolAddress((void**)&csr1,  g_csr1);
    cudaGetSymbolAddress((void**)&wh0,   g_wh0);
    cudaGetSymbolAddress((void**)&wm0,   g_wm0);
    cudaGetSymbolAddress((void**)&wh1,   g_wh1);
    cudaGetSymbolAddress((void**)&wm1,   g_wm1);
    cudaGetSymbolAddress((void**)&kwh,   g_kwh);
    cudaGetSymbolAddress((void**)&kwm,   g_kwm);

    static cudaStream_t sB = nullptr;
    static cudaEvent_t evFork = nullptr, evJoinCSR = nullptr, evJoinW = nullptr;
    if (sB == nullptr) {
        cudaStreamCreateWithFlags(&sB, cudaStreamNonBlocking);
        cudaEventCreateWithFlags(&evFork, cudaEventDisableTiming);
        cudaEventCreateWithFlags(&evJoinCSR, cudaEventDisableTiming);
        cudaEventCreateWithFlags(&evJoinW, cudaEventDisableTiming);
    }

    cudaFuncSetAttribute(mma_gemm_bias_kernel,
                         cudaFuncAttributeMaxDynamicSharedMemorySize, GEMM_SMEM_BYTES);
    cudaFuncSetAttribute(sem_mma_kernel,
                         cudaFuncAttributeMaxDynamicSharedMemorySize, GEMM_SMEM_BYTES);

    // ---- fork: weight splits + CSR build on stream B (input-only deps) ------
    cudaEventRecord(evFork, 0);
    cudaStreamWaitEvent(sB, evFork, 0);

    // W_add/W_del split (tiny): must finish before proj GEMM
    split_kernel<<<dim3(FOUT * K_IN / 4 / 256, 2), 256, 0, sB>>>(
        W_add, wh0, wm0, W_del, wh1, wm1, FOUT * K_IN / 4);
    cudaEventRecord(evJoinW, sB);

    dim3 ew_grid((E_EDGES + 255) / 256, 2);
    cudaMemsetAsync(deg0, 0, (size_t)N_NODES * sizeof(int), sB);
    cudaMemsetAsync(deg1, 0, (size_t)N_NODES * sizeof(int), sB);
    deg_kernel<<<ew_grid, 256, 0, sB>>>(ei_ad, deg0, ei_dd, deg1, E_EDGES);
    scan_kernel<<<2, 1024, 0, sB>>>(deg0, start0, cur0, deg1, start1, cur1);
    fill_kernel<<<ew_grid, 256, 0, sB>>>(ei_ad, cur0, csr0, ei_dd, cur1, csr1, E_EDGES);
    split_kernel<<<dim3(FOUT * FOUT / 4 / 256, 1), 256, 0, sB>>>(
        k_W, kwh, kwm, k_W, kwh, kwm, FOUT * FOUT / 4);
    cudaEventRecord(evJoinCSR, sB);

    // ---- main stream ---------------------------------------------------------
    cudaMemsetAsync(sad,   0, (size_t)N_NODES * 2 * sizeof(float), 0);
    cudaMemsetAsync(sdd,   0, (size_t)N_NODES * 2 * sizeof(float), 0);
    cudaMemsetAsync(score, 0, 2 * sizeof(float), 0);

    cudaStreamWaitEvent(0, evJoinW, 0);   // proj GEMM needs split weights

    dim3 gemm_grid(1, (N_NODES + 127) / 128, 2);     // (1, 157, 2)
    mma_gemm_bias_kernel<<<gemm_grid, 512, GEMM_SMEM_BYTES>>>(
        x_add, wh0, wm0, b_add, ha,
        x_del, wh1, wm1, b_del, hd, N_NODES, K_IN);

    dots_kernel<<<N_NODES / 8, 256>>>(ha, hd, att_ad_s, att_ad_d, att_dd_s, att_dd_d,
                                      asad, adad, asdd, addd, N_NODES);

    edge_w_kernel<<<ew_grid, 256>>>(ei_ad, asad, adad, wad, sad,
                                    ei_dd, asdd, addd, wdd, sdd, E_EDGES);

    // ---- join: gather needs CSR (stream B) + weights (stream 0) -------------
    cudaStreamWaitEvent(0, evJoinCSR, 0);

    dim3 ga_grid((N_NODES + 7) / 8, 2);
    gather_kernel<<<ga_grid, 256>>>(
        ei_ad, csr0, start0, cur0, wad, sad, ha, oad,
        ei_dd, csr1, start1, cur1, wdd, sdd, hd, odd, N_NODES);

    dim3 sem_grid(1, (N_NODES + 127) / 128, 2);
    sem_mma_kernel<<<sem_grid, 512, GEMM_SMEM_BYTES>>>(
        oad, odd, kwh, kwm, k_b, q, score, N_NODES);

    final_kernel<<<(N_SEL * 64) / 256, 256>>>(del_idx, oad, odd, score, (float*)d_out);
}

// round 17
// speedup vs baseline: 1.1175x; 1.1175x over previous
#include <cuda_runtime.h>
#include <cuda_bf16.h>
#include <math.h>

#define N_NODES 20000
#define E_EDGES 200000
#define FOUT    256
#define K_IN    768
#define N_SEL   4096

// ---------------- device scratch (static globals: allocation-free) ----------
__device__ float g_ha[(size_t)N_NODES * FOUT];
__device__ float g_hd[(size_t)N_NODES * FOUT];
__device__ float g_oad[(size_t)N_NODES * FOUT];
__device__ float g_odd[(size_t)N_NODES * FOUT];
__device__ float g_as_ad[N_NODES * 2];
__device__ float g_ad_ad[N_NODES * 2];
__device__ float g_as_dd[N_NODES * 2];
__device__ float g_ad_dd[N_NODES * 2];
__device__ float g_w_ad[E_EDGES * 2];
__device__ float g_w_dd[E_EDGES * 2];
__device__ float g_s_ad[N_NODES * 2];
__device__ float g_s_dd[N_NODES * 2];
__device__ float g_score[2];
// CSR scratch
__device__ int g_deg0[N_NODES];
__device__ int g_deg1[N_NODES];
__device__ int g_start0[N_NODES];
__device__ int g_start1[N_NODES];
__device__ int g_cur0[N_NODES];
__device__ int g_cur1[N_NODES];
__device__ int g_csr0[E_EDGES];
__device__ int g_csr1[E_EDGES];
// bf16-split mirrors (hi/mid) of the WEIGHTS only (small, split once)
__device__ __nv_bfloat16 g_wh0[FOUT * K_IN];
__device__ __nv_bfloat16 g_wm0[FOUT * K_IN];
__device__ __nv_bfloat16 g_wh1[FOUT * K_IN];
__device__ __nv_bfloat16 g_wm1[FOUT * K_IN];
__device__ __nv_bfloat16 g_kwh[FOUT * FOUT];
__device__ __nv_bfloat16 g_kwm[FOUT * FOUT];

// ---------------- helpers ---------------------------------------------------
__device__ __forceinline__ float dot4(float4 a, float4 b) {
    return a.x * b.x + a.y * b.y + a.z * b.z + a.w * b.w;
}

__device__ __forceinline__ float warp_sum(float v) {
#pragma unroll
    for (int o = 16; o > 0; o >>= 1) v += __shfl_xor_sync(0xffffffffu, v, o);
    return v;
}

// bf16 two-component split: x ~= hi + mid, error O(2^-18 * x)
__device__ __forceinline__ void bsplit(float x, __nv_bfloat16& h, __nv_bfloat16& m) {
    h = __float2bfloat16_rn(x);
    m = __float2bfloat16_rn(x - __bfloat162float(h));
}

// m16n8k16 bf16 MMA, fp32 accumulate
__device__ __forceinline__ void mma_bf16(float* c, const unsigned* a, const unsigned* b) {
    asm volatile(
        "mma.sync.aligned.m16n8k16.row.col.f32.bf16.bf16.f32 "
        "{%0,%1,%2,%3}, {%4,%5,%6,%7}, {%8,%9}, {%0,%1,%2,%3};"
        : "+f"(c[0]), "+f"(c[1]), "+f"(c[2]), "+f"(c[3])
        : "r"(a[0]), "r"(a[1]), "r"(a[2]), "r"(a[3]), "r"(b[0]), "r"(b[1]));
}

__device__ __forceinline__ void cp_async16(void* sdst, const void* gsrc) {
    unsigned s = (unsigned)__cvta_generic_to_shared(sdst);
    asm volatile("cp.async.cg.shared.global [%0], [%1], 16;" :: "r"(s), "l"(gsrc)
                 : "memory");
}

#define SA 40                  // bf16 row stride: conflict-free fragment loads
#define ATILE (128 * SA)       // one 128x32 bf16 tile (SA-padded)
// smem: fp32 A staging (double) + Ah/Am (single) + Bh/Bm (double, pre-split)
#define GEMM_SMEM_BYTES (2*4096*4 + 2*ATILE*2 + 4*ATILE*2)   // 94208

// ---------------- kernel 0: fp32 -> bf16 hi/mid split (weights only) --------
__global__ __launch_bounds__(256) void split_kernel(
    const float* __restrict__ s0, __nv_bfloat16* __restrict__ h0,
    __nv_bfloat16* __restrict__ m0,
    const float* __restrict__ s1, __nv_bfloat16* __restrict__ h1,
    __nv_bfloat16* __restrict__ m1, int n4)
{
    const float* s = blockIdx.y ? s1 : s0;
    __nv_bfloat16* h = blockIdx.y ? h1 : h0;
    __nv_bfloat16* m = blockIdx.y ? m1 : m0;
    int i = blockIdx.x * 256 + threadIdx.x;
    if (i >= n4) return;
    float4 v = ((const float4*)s)[i];
    __nv_bfloat16 h0v, m0v, h1v, m1v, h2v, m2v, h3v, m3v;
    bsplit(v.x, h0v, m0v); bsplit(v.y, h1v, m1v);
    bsplit(v.z, h2v, m2v); bsplit(v.w, h3v, m3v);
    union { __nv_bfloat162 b[2]; uint2 u; } ph, pm;
    ph.b[0] = __nv_bfloat162(h0v, h1v); ph.b[1] = __nv_bfloat162(h2v, h3v);
    pm.b[0] = __nv_bfloat162(m0v, m1v); pm.b[1] = __nv_bfloat162(m2v, m3v);
    ((uint2*)h)[i] = ph.u;
    ((uint2*)m)[i] = pm.u;
}

// ---------------- kernel 1: h = x @ W^T + b ---------------------------------
// Round-13 skeleton: 256 thr, 128x128 tile, 2 CTA/SM. A staged fp32 and
// split in-kernel; W arrives PRE-SPLIT bf16 via cp.async (no W convert).
__global__ __launch_bounds__(256, 2) void mma_gemm_bias_kernel(
    const float* __restrict__ A0,
    const __nv_bfloat16* __restrict__ Wh0, const __nv_bfloat16* __restrict__ Wm0,
    const float* __restrict__ bias0, float* __restrict__ C0,
    const float* __restrict__ A1,
    const __nv_bfloat16* __restrict__ Wh1, const __nv_bfloat16* __restrict__ Wm1,
    const float* __restrict__ bias1, float* __restrict__ C1,
    int M, int K)
{
    extern __shared__ __align__(16) char dynsmem[];
    float* SAf = (float*)dynsmem;                           // [2][4096] fp32
    __nv_bfloat16* Ah = (__nv_bfloat16*)(SAf + 2 * 4096);   // [ATILE]
    __nv_bfloat16* Am = Ah + ATILE;                         // [ATILE]
    __nv_bfloat16* Bh = Am + ATILE;                         // [2][ATILE]
    __nv_bfloat16* Bm = Bh + 2 * ATILE;                     // [2][ATILE]

    const float* A = blockIdx.z ? A1 : A0;
    const __nv_bfloat16* Whg = blockIdx.z ? Wh1 : Wh0;
    const __nv_bfloat16* Wmg = blockIdx.z ? Wm1 : Wm0;
    const float* bias = blockIdx.z ? bias1 : bias0;
    float*       C    = blockIdx.z ? C1 : C0;

    const int tid = threadIdx.x;
    const int lane = tid & 31;
    const int wid = tid >> 5;
    const int warp_m = wid & 3;          // 4 warps over M (32 rows each)
    const int warp_n = wid >> 2;         // 2 warps over N (64 cols each)
    const int rowBase = blockIdx.y * 128;
    const int colBase = blockIdx.x * 128;

    float acc[2][8][4];
#pragma unroll
    for (int mt = 0; mt < 2; mt++)
#pragma unroll
        for (int nt = 0; nt < 8; nt++)
#pragma unroll
            for (int i = 0; i < 4; i++) acc[mt][nt][i] = 0.f;

    const int lrow = lane >> 2;
    const int lk = (lane & 3) * 2;

    auto issue_chunk = [&](int k0, int buf) {
        // A: 128 rows x 32 k fp32 = 1024 x 16B, 4 per thread
#pragma unroll
        for (int i = 0; i < 4; i++) {
            int idx = tid + i * 256;
            int row = idx >> 3;
            int f4 = idx & 7;
            int grow = rowBase + row; if (grow > M - 1) grow = M - 1;
            cp_async16(SAf + buf * 4096 + idx * 4, A + (size_t)grow * K + k0 + f4 * 4);
        }
        // Bh/Bm: 128 rows x 32 k bf16 = 512 x 16B each, 2+2 per thread
#pragma unroll
        for (int i = 0; i < 2; i++) {
            int idx = tid + i * 256;
            int row = idx >> 2;
            int f4 = idx & 3;
            cp_async16(Bh + buf * ATILE + row * SA + f4 * 8,
                       Whg + (size_t)(colBase + row) * K + k0 + f4 * 8);
            cp_async16(Bm + buf * ATILE + row * SA + f4 * 8,
                       Wmg + (size_t)(colBase + row) * K + k0 + f4 * 8);
        }
        asm volatile("cp.async.commit_group;" ::: "memory");
    };

    const int nChunks = K / 32;
    issue_chunk(0, 0);

    for (int kc = 0; kc < nChunks; kc++) {
        const int buf = kc & 1;
        if (kc + 1 < nChunks) {
            issue_chunk((kc + 1) * 32, buf ^ 1);
            asm volatile("cp.async.wait_group 1;" ::: "memory");
        } else {
            asm volatile("cp.async.wait_group 0;" ::: "memory");
        }
        // convert A slots only (half the work of round 13)
#pragma unroll
        for (int i = 0; i < 4; i++) {
            int idx = tid + i * 256;
            int row = idx >> 3;
            int f4 = idx & 7;
            float4 v = ((const float4*)(SAf + buf * 4096))[idx];
            __nv_bfloat16 h0, m0, h1, m1, h2, m2, h3, m3;
            bsplit(v.x, h0, m0); bsplit(v.y, h1, m1);
            bsplit(v.z, h2, m2); bsplit(v.w, h3, m3);
            int o = row * SA + f4 * 4;
            *(__nv_bfloat162*)&Ah[o]     = __nv_bfloat162(h0, h1);
            *(__nv_bfloat162*)&Ah[o + 2] = __nv_bfloat162(h2, h3);
            *(__nv_bfloat162*)&Am[o]     = __nv_bfloat162(m0, m1);
            *(__nv_bfloat162*)&Am[o + 2] = __nv_bfloat162(m2, m3);
        }
        __syncthreads();
        const __nv_bfloat16* BhS = Bh + buf * ATILE;
        const __nv_bfloat16* BmS = Bm + buf * ATILE;

#pragma unroll
        for (int kk = 0; kk < 2; kk++) {
            const int kb = kk * 16;
            unsigned ah[2][4], am[2][4];
#pragma unroll
            for (int mt = 0; mt < 2; mt++) {
                int r0 = (warp_m * 32 + mt * 16 + lrow) * SA + kb + lk;
                ah[mt][0] = *(const unsigned*)&Ah[r0];
                ah[mt][1] = *(const unsigned*)&Ah[r0 + 8 * SA];
                ah[mt][2] = *(const unsigned*)&Ah[r0 + 8];
                ah[mt][3] = *(const unsigned*)&Ah[r0 + 8 * SA + 8];
                am[mt][0] = *(const unsigned*)&Am[r0];
                am[mt][1] = *(const unsigned*)&Am[r0 + 8 * SA];
                am[mt][2] = *(const unsigned*)&Am[r0 + 8];
                am[mt][3] = *(const unsigned*)&Am[r0 + 8 * SA + 8];
            }
#pragma unroll
            for (int nt = 0; nt < 8; nt++) {
                int n0 = (warp_n * 64 + nt * 8 + lrow) * SA + kb + lk;
                unsigned bh[2], bm[2];
                bh[0] = *(const unsigned*)&BhS[n0];
                bh[1] = *(const unsigned*)&BhS[n0 + 8];
                bm[0] = *(const unsigned*)&BmS[n0];
                bm[1] = *(const unsigned*)&BmS[n0 + 8];
#pragma unroll
                for (int mt = 0; mt < 2; mt++) {
                    mma_bf16(acc[mt][nt], ah[mt], bh);
                    mma_bf16(acc[mt][nt], ah[mt], bm);
                    mma_bf16(acc[mt][nt], am[mt], bh);
                }
            }
        }
        __syncthreads();
    }

#pragma unroll
    for (int mt = 0; mt < 2; mt++) {
        int r = rowBase + warp_m * 32 + mt * 16 + lrow;
#pragma unroll
        for (int nt = 0; nt < 8; nt++) {
            int c = colBase + warp_n * 64 + nt * 8 + lk;
            float b0 = bias[c], b1 = bias[c + 1];
            if (r < M) {
                float2 o = make_float2(acc[mt][nt][0] + b0, acc[mt][nt][1] + b1);
                *(float2*)&C[(size_t)r * FOUT + c] = o;
            }
            if (r + 8 < M) {
                float2 o = make_float2(acc[mt][nt][2] + b0, acc[mt][nt][3] + b1);
                *(float2*)&C[(size_t)(r + 8) * FOUT + c] = o;
            }
        }
    }
}

// ---------------- kernel 2: per-node attention dot products -----------------
__global__ __launch_bounds__(256) void dots_kernel(
    const float* __restrict__ ha, const float* __restrict__ hd,
    const float* __restrict__ att_ad_s, const float* __restrict__ att_ad_d,
    const float* __restrict__ att_dd_s, const float* __restrict__ att_dd_d,
    float* __restrict__ as_ad, float* __restrict__ ad_ad,
    float* __restrict__ as_dd, float* __restrict__ ad_dd, int N)
{
    int warp = (blockIdx.x * blockDim.x + threadIdx.x) >> 5;
    int lane = threadIdx.x & 31;
    if (warp >= N) return;
    const float4* ha4 = (const float4*)(ha + (size_t)warp * FOUT);
    const float4* hd4 = (const float4*)(hd + (size_t)warp * FOUT);
    float4 a0 = ha4[lane], a1 = ha4[32 + lane];
    float4 d0 = hd4[lane], d1 = hd4[32 + lane];

    const float4* v;
    float r;
    v = (const float4*)att_ad_s;
    r = warp_sum(dot4(a0, v[lane]));          if (lane == 0) as_ad[2 * warp + 0] = r;
    r = warp_sum(dot4(a1, v[32 + lane]));     if (lane == 0) as_ad[2 * warp + 1] = r;
    v = (const float4*)att_ad_d;
    r = warp_sum(dot4(d0, v[lane]));          if (lane == 0) ad_ad[2 * warp + 0] = r;
    r = warp_sum(dot4(d1, v[32 + lane]));     if (lane == 0) ad_ad[2 * warp + 1] = r;
    v = (const float4*)att_dd_s;
    r = warp_sum(dot4(d0, v[lane]));          if (lane == 0) as_dd[2 * warp + 0] = r;
    r = warp_sum(dot4(d1, v[32 + lane]));     if (lane == 0) as_dd[2 * warp + 1] = r;
    v = (const float4*)att_dd_d;
    r = warp_sum(dot4(d0, v[lane]));          if (lane == 0) ad_dd[2 * warp + 0] = r;
    r = warp_sum(dot4(d1, v[32 + lane]));     if (lane == 0) ad_dd[2 * warp + 1] = r;
}

// ---------------- kernel 3: edge weights + denominators ---------------------
__global__ __launch_bounds__(256) void edge_w_kernel(
    const int* __restrict__ ei0, const float* __restrict__ as0,
    const float* __restrict__ ad0, float* __restrict__ w0, float* __restrict__ s0,
    const int* __restrict__ ei1, const float* __restrict__ as1,
    const float* __restrict__ ad1, float* __restrict__ w1, float* __restrict__ s1,
    int E)
{
    const int* ei = blockIdx.y ? ei1 : ei0;
    const float* asrc = blockIdx.y ? as1 : as0;
    const float* adst = blockIdx.y ? ad1 : ad0;
    float* w = blockIdx.y ? w1 : w0;
    float* s = blockIdx.y ? s1 : s0;
    int e = blockIdx.x * blockDim.x + threadIdx.x;
    if (e >= E) return;
    int src = ei[e];
    int dst = ei[E + e];
#pragma unroll
    for (int h = 0; h < 2; h++) {
        float v = asrc[2 * src + h] + adst[2 * dst + h];
        v = v > 0.f ? v : 0.2f * v;
        float we = expf(v);
        w[2 * e + h] = we;
        atomicAdd(&s[2 * dst + h], we);
    }
}

// ---------------- CSR build (stream B, input-only dependencies) -------------
__global__ __launch_bounds__(256) void deg_kernel(
    const int* __restrict__ ei0, int* __restrict__ d0,
    const int* __restrict__ ei1, int* __restrict__ d1, int E)
{
    const int* ei = blockIdx.y ? ei1 : ei0;
    int* deg = blockIdx.y ? d1 : d0;
    int e = blockIdx.x * blockDim.x + threadIdx.x;
    if (e < E) atomicAdd(&deg[ei[E + e]], 1);
}

// exclusive scan of degrees — shfl-based 3-level, 2 barriers total
__global__ __launch_bounds__(1024) void scan_kernel(
    const int* __restrict__ deg0, int* __restrict__ start0, int* __restrict__ cur0,
    const int* __restrict__ deg1, int* __restrict__ start1, int* __restrict__ cur1)
{
    const int* deg = blockIdx.x ? deg1 : deg0;
    int* start = blockIdx.x ? start1 : start0;
    int* cur   = blockIdx.x ? cur1 : cur0;
    __shared__ int wsum[32];
    const int t = threadIdx.x;
    const int lane = t & 31;
    const int w = t >> 5;
    const int base = t * 20;
    int vals[20];
    int local = 0;
#pragma unroll
    for (int i = 0; i < 20; i++) {
        int idx = base + i;
        vals[i] = (idx < N_NODES) ? deg[idx] : 0;
        local += vals[i];
    }
    int inc = local;
#pragma unroll
    for (int o = 1; o < 32; o <<= 1) {
        int v = __shfl_up_sync(0xffffffffu, inc, o);
        if (lane >= o) inc += v;
    }
    if (lane == 31) wsum[w] = inc;
    __syncthreads();
    if (w == 0) {
        int v = wsum[lane];
        int inc2 = v;
#pragma unroll
        for (int o = 1; o < 32; o <<= 1) {
            int u = __shfl_up_sync(0xffffffffu, inc2, o);
            if (lane >= o) inc2 += u;
        }
        wsum[lane] = inc2 - v;
    }
    __syncthreads();
    int run = wsum[w] + inc - local;
#pragma unroll
    for (int i = 0; i < 20; i++) {
        int idx = base + i;
        if (idx < N_NODES) {
            start[idx] = run;
            cur[idx] = run;
            run += vals[i];
        }
    }
}

__global__ __launch_bounds__(256) void fill_kernel(
    const int* __restrict__ ei0, int* __restrict__ cur0, int* __restrict__ csr0,
    const int* __restrict__ ei1, int* __restrict__ cur1, int* __restrict__ csr1,
    int E)
{
    const int* ei = blockIdx.y ? ei1 : ei0;
    int* cur = blockIdx.y ? cur1 : cur0;
    int* csr = blockIdx.y ? csr1 : csr0;
    int e = blockIdx.x * blockDim.x + threadIdx.x;
    if (e >= E) return;
    int dst = ei[E + e];
    int pos = atomicAdd(&cur[dst], 1);
    csr[pos] = e;
}

// ---------------- kernel 4: gather (warp per node, window-batched indices) --
__global__ __launch_bounds__(256) void gather_kernel(
    const int* __restrict__ ei0, const int* __restrict__ csr0,
    const int* __restrict__ start0, const int* __restrict__ end0,
    const float* __restrict__ w0, const float* __restrict__ s0,
    const float* __restrict__ h0, float* __restrict__ o0,
    const int* __restrict__ ei1, const int* __restrict__ csr1,
    const int* __restrict__ start1, const int* __restrict__ end1,
    const float* __restrict__ w1, const float* __restrict__ s1,
    const float* __restrict__ h1, float* __restrict__ o1,
    int N)
{
    const int* ei    = blockIdx.y ? ei1 : ei0;
    const int* csr   = blockIdx.y ? csr1 : csr0;
    const int* start = blockIdx.y ? start1 : start0;
    const int* end   = blockIdx.y ? end1 : end0;
    const float* w   = blockIdx.y ? w1 : w0;
    const float* s   = blockIdx.y ? s1 : s0;
    const float* h   = blockIdx.y ? h1 : h0;
    float* out       = blockIdx.y ? o1 : o0;

    int gw = (blockIdx.x * blockDim.x + threadIdx.x) >> 5;
    int lane = threadIdx.x & 31;
    if (gw >= N) return;
    int st = start[gw], en = end[gw];
    float4 a0 = make_float4(0.f, 0.f, 0.f, 0.f);
    float4 a1 = make_float4(0.f, 0.f, 0.f, 0.f);
    for (int wst = st; wst < en; wst += 32) {
        int j = wst + lane;
        int srcv = 0;
        float2 wv = make_float2(0.f, 0.f);
        if (j < en) {
            int e = csr[j];
            srcv = ei[e];
            wv = ((const float2*)w)[e];
        }
        int cnt = en - wst; if (cnt > 32) cnt = 32;
        for (int t = 0; t < cnt; t++) {
            int src = __shfl_sync(0xffffffffu, srcv, t);
            float we0 = __shfl_sync(0xffffffffu, wv.x, t);
            float we1 = __shfl_sync(0xffffffffu, wv.y, t);
            const float4* h4 = (const float4*)(h + (size_t)src * FOUT);
            float4 v0 = h4[lane];
            float4 v1 = h4[32 + lane];
            a0.x += we0 * v0.x; a0.y += we0 * v0.y;
            a0.z += we0 * v0.z; a0.w += we0 * v0.w;
            a1.x += we1 * v1.x; a1.y += we1 * v1.y;
            a1.z += we1 * v1.z; a1.w += we1 * v1.w;
        }
    }
    float is0 = 1.f / (s[2 * gw + 0] + 1e-16f);
    float is1 = 1.f / (s[2 * gw + 1] + 1e-16f);
    float4 r0 = make_float4(fmaxf(a0.x * is0, 0.f), fmaxf(a0.y * is0, 0.f),
                            fmaxf(a0.z * is0, 0.f), fmaxf(a0.w * is0, 0.f));
    float4 r1 = make_float4(fmaxf(a1.x * is1, 0.f), fmaxf(a1.y * is1, 0.f),
                            fmaxf(a1.z * is1, 0.f), fmaxf(a1.w * is1, 0.f));
    float* o = out + (size_t)gw * FOUT;
    ((float4*)o)[lane] = r0;
    ((float4*)o)[32 + lane] = r1;
}

// ---------------- kernel 5: semantic attention score ------------------------
// Same skeleton: 256 thr, 128x128 tile, 2 CTA/SM, A split in-kernel (with
// relu), kW arrives pre-split bf16. K = 256.
__global__ __launch_bounds__(256, 2) void sem_mma_kernel(
    const float* __restrict__ A0, const float* __restrict__ A1,
    const __nv_bfloat16* __restrict__ kWh, const __nv_bfloat16* __restrict__ kWm,
    const float* __restrict__ kb, const float* __restrict__ q,
    float* __restrict__ score, int M)
{
    extern __shared__ __align__(16) char dynsmem[];
    float* SAf = (float*)dynsmem;
    __nv_bfloat16* Ah = (__nv_bfloat16*)(SAf + 2 * 4096);
    __nv_bfloat16* Am = Ah + ATILE;
    __nv_bfloat16* Bh = Am + ATILE;
    __nv_bfloat16* Bm = Bh + 2 * ATILE;
    __shared__ float sred[256];

    const float* A = blockIdx.z ? A1 : A0;
    const int K = FOUT;   // 256
    const int tid = threadIdx.x;
    const int lane = tid & 31;
    const int wid = tid >> 5;
    const int warp_m = wid & 3;
    const int warp_n = wid >> 2;
    const int rowBase = blockIdx.y * 128;
    const int colBase = blockIdx.x * 128;

    float acc[2][8][4];
#pragma unroll
    for (int mt = 0; mt < 2; mt++)
#pragma unroll
        for (int nt = 0; nt < 8; nt++)
#pragma unroll
            for (int i = 0; i < 4; i++) acc[mt][nt][i] = 0.f;

    const int lrow = lane >> 2;
    const int lk = (lane & 3) * 2;

    auto issue_chunk = [&](int k0, int buf) {
#pragma unroll
        for (int i = 0; i < 4; i++) {
            int idx = tid + i * 256;
            int row = idx >> 3;
            int f4 = idx & 7;
            int grow = rowBase + row; if (grow > M - 1) grow = M - 1;
            cp_async16(SAf + buf * 4096 + idx * 4, A + (size_t)grow * K + k0 + f4 * 4);
        }
#pragma unroll
        for (int i = 0; i < 2; i++) {
            int idx = tid + i * 256;
            int row = idx >> 2;
            int f4 = idx & 3;
            cp_async16(Bh + buf * ATILE + row * SA + f4 * 8,
                       kWh + (size_t)(colBase + row) * K + k0 + f4 * 8);
            cp_async16(Bm + buf * ATILE + row * SA + f4 * 8,
                       kWm + (size_t)(colBase + row) * K + k0 + f4 * 8);
        }
        asm volatile("cp.async.commit_group;" ::: "memory");
    };

    const int nChunks = K / 32;   // 8
    issue_chunk(0, 0);

    for (int kc = 0; kc < nChunks; kc++) {
        const int buf = kc & 1;
        if (kc + 1 < nChunks) {
            issue_chunk((kc + 1) * 32, buf ^ 1);
            asm volatile("cp.async.wait_group 1;" ::: "memory");
        } else {
            asm volatile("cp.async.wait_group 0;" ::: "memory");
        }
#pragma unroll
        for (int i = 0; i < 4; i++) {
            int idx = tid + i * 256;
            int row = idx >> 3;
            int f4 = idx & 7;
            float4 v = ((const float4*)(SAf + buf * 4096))[idx];
            v.x = fmaxf(v.x, 0.f); v.y = fmaxf(v.y, 0.f);   // relu (idempotent)
            v.z = fmaxf(v.z, 0.f); v.w = fmaxf(v.w, 0.f);
            __nv_bfloat16 h0, m0, h1, m1, h2, m2, h3, m3;
            bsplit(v.x, h0, m0); bsplit(v.y, h1, m1);
            bsplit(v.z, h2, m2); bsplit(v.w, h3, m3);
            int o = row * SA + f4 * 4;
            *(__nv_bfloat162*)&Ah[o]     = __nv_bfloat162(h0, h1);
            *(__nv_bfloat162*)&Ah[o + 2] = __nv_bfloat162(h2, h3);
            *(__nv_bfloat162*)&Am[o]     = __nv_bfloat162(m0, m1);
            *(__nv_bfloat162*)&Am[o + 2] = __nv_bfloat162(m2, m3);
        }
        __syncthreads();
        const __nv_bfloat16* BhS = Bh + buf * ATILE;
        const __nv_bfloat16* BmS = Bm + buf * ATILE;

#pragma unroll
        for (int kk = 0; kk < 2; kk++) {
            const int kb2 = kk * 16;
            unsigned ah[2][4], am[2][4];
#pragma unroll
            for (int mt = 0; mt < 2; mt++) {
                int r0 = (warp_m * 32 + mt * 16 + lrow) * SA + kb2 + lk;
                ah[mt][0] = *(const unsigned*)&Ah[r0];
                ah[mt][1] = *(const unsigned*)&Ah[r0 + 8 * SA];
                ah[mt][2] = *(const unsigned*)&Ah[r0 + 8];
                ah[mt][3] = *(const unsigned*)&Ah[r0 + 8 * SA + 8];
                am[mt][0] = *(const unsigned*)&Am[r0];
                am[mt][1] = *(const unsigned*)&Am[r0 + 8 * SA];
                am[mt][2] = *(const unsigned*)&Am[r0 + 8];
                am[mt][3] = *(const unsigned*)&Am[r0 + 8 * SA + 8];
            }
#pragma unroll
            for (int nt = 0; nt < 8; nt++) {
                int n0 = (warp_n * 64 + nt * 8 + lrow) * SA + kb2 + lk;
                unsigned bh[2], bm[2];
                bh[0] = *(const unsigned*)&BhS[n0];
                bh[1] = *(const unsigned*)&BhS[n0 + 8];
                bm[0] = *(const unsigned*)&BmS[n0];
                bm[1] = *(const unsigned*)&BmS[n0 + 8];
#pragma unroll
                for (int mt = 0; mt < 2; mt++) {
                    mma_bf16(acc[mt][nt], ah[mt], bh);
                    mma_bf16(acc[mt][nt], ah[mt], bm);
                    mma_bf16(acc[mt][nt], am[mt], bh);
                }
            }
        }
        __syncthreads();
    }

    float local = 0.f;
#pragma unroll
    for (int mt = 0; mt < 2; mt++) {
        int r = rowBase + warp_m * 32 + mt * 16 + lrow;
#pragma unroll
        for (int nt = 0; nt < 8; nt++) {
            int c = colBase + warp_n * 64 + nt * 8 + lk;
            float kb0 = kb[c], kb1 = kb[c + 1];
            float q0 = q[c], q1 = q[c + 1];
            if (r < M)
                local += tanhf(acc[mt][nt][0] + kb0) * q0 + tanhf(acc[mt][nt][1] + kb1) * q1;
            if (r + 8 < M)
                local += tanhf(acc[mt][nt][2] + kb0) * q0 + tanhf(acc[mt][nt][3] + kb1) * q1;
        }
    }
    sred[tid] = local;
    __syncthreads();
#pragma unroll
    for (int st = 128; st > 0; st >>= 1) {
        if (tid < st) sred[tid] += sred[tid + st];
        __syncthreads();
    }
    if (tid == 0) atomicAdd(&score[blockIdx.z], sred[0] * (1.0f / (float)N_NODES));
}

// ---------------- kernel 6: 2-way softmax + gather --------------------------
__global__ __launch_bounds__(256) void final_kernel(
    const int* __restrict__ idx,
    const float* __restrict__ oa, const float* __restrict__ od,
    const float* __restrict__ score, float* __restrict__ out)
{
    int t = blockIdx.x * blockDim.x + threadIdx.x;
    if (t >= N_SEL * 64) return;
    float s0 = score[0], s1 = score[1];
    float m = fmaxf(s0, s1);
    float e0 = expf(s0 - m), e1 = expf(s1 - m);
    float inv = 1.f / (e0 + e1);
    float a0 = e0 * inv, a1 = e1 * inv;
    int sel = t >> 6, c4 = t & 63;
    int row = idx[sel];
    float4 u = ((const float4*)(oa + (size_t)row * FOUT))[c4];
    float4 v = ((const float4*)(od + (size_t)row * FOUT))[c4];
    float4 r;
    r.x = a0 * fmaxf(u.x, 0.f) + a1 * fmaxf(v.x, 0.f);
    r.y = a0 * fmaxf(u.y, 0.f) + a1 * fmaxf(v.y, 0.f);
    r.z = a0 * fmaxf(u.z, 0.f) + a1 * fmaxf(v.z, 0.f);
    r.w = a0 * fmaxf(u.w, 0.f) + a1 * fmaxf(v.w, 0.f);
    ((float4*)out)[t] = r;
}

// ---------------- launch ----------------------------------------------------
extern "C" void kernel_launch(void* const* d_in, const int* in_sizes, int n_in,
                              void* d_out, int out_size)
{
    (void)in_sizes; (void)n_in; (void)out_size;
    const float* x_add    = (const float*)d_in[0];
    const float* x_del    = (const float*)d_in[1];
    const float* W_add    = (const float*)d_in[2];
    const float* b_add    = (const float*)d_in[3];
    const float* W_del    = (const float*)d_in[4];
    const float* b_del    = (const float*)d_in[5];
    const float* att_ad_s = (const float*)d_in[6];
    const float* att_ad_d = (const float*)d_in[7];
    // d_in[8..11] = att_da_*/att_aa_* — metapaths feed a discarded output: skipped
    const float* att_dd_s = (const float*)d_in[12];
    const float* att_dd_d = (const float*)d_in[13];
    const float* k_W      = (const float*)d_in[14];
    const float* k_b      = (const float*)d_in[15];
    const float* q        = (const float*)d_in[16];
    const int*   ei_ad    = (const int*)d_in[17];
    // d_in[18], d_in[19] = ei_da, ei_aa: skipped
    const int*   ei_dd    = (const int*)d_in[20];
    const int*   del_idx  = (const int*)d_in[21];

    float *ha, *hd, *oad, *odd, *asad, *adad, *asdd, *addd, *wad, *wdd, *sad, *sdd, *score;
    int *deg0, *deg1, *start0, *start1, *cur0, *cur1, *csr0, *csr1;
    __nv_bfloat16 *wh0, *wm0, *wh1, *wm1, *kwh, *kwm;
    cudaGetSymbolAddress((void**)&ha,    g_ha);
    cudaGetSymbolAddress((void**)&hd,    g_hd);
    cudaGetSymbolAddress((void**)&oad,   g_oad);
    cudaGetSymbolAddress((void**)&odd,   g_odd);
    cudaGetSymbolAddress((void**)&asad,  g_as_ad);
    cudaGetSymbolAddress((void**)&adad,  g_ad_ad);
    cudaGetSymbolAddress((void**)&asdd,  g_as_dd);
    cudaGetSymbolAddress((void**)&addd,  g_ad_dd);
    cudaGetSymbolAddress((void**)&wad,   g_w_ad);
    cudaGetSymbolAddress((void**)&wdd,   g_w_dd);
    cudaGetSymbolAddress((void**)&sad,   g_s_ad);
    cudaGetSymbolAddress((void**)&sdd,   g_s_dd);
    cudaGetSymbolAddress((void**)&score, g_score);
    cudaGetSymbolAddress((void**)&deg0,  g_deg0);
    cudaGetSymbolAddress((void**)&deg1,  g_deg1);
    cudaGetSymbolAddress((void**)&start0, g_start0);
    cudaGetSymbolAddress((void**)&start1, g_start1);
    cudaGetSymbolAddress((void**)&cur0,  g_cur0);
    cudaGetSymbolAddress((void**)&cur1,  g_cur1);
    cudaGetSymbolAddress((void**)&csr0,  g_csr0);
    cudaGetSymbolAddress((void**)&csr1,  g_csr1);
    cudaGetSymbolAddress((void**)&wh0,   g_wh0);
    cudaGetSymbolAddress((void**)&wm0,   g_wm0);
    cudaGetSymbolAddress((void**)&wh1,   g_wh1);
    cudaGetSymbolAddress((void**)&wm1,   g_wm1);
    cudaGetSymbolAddress((void**)&kwh,   g_kwh);
    cudaGetSymbolAddress((void**)&kwm,   g_kwm);

    static cudaStream_t sB = nullptr;
    static cudaEvent_t evFork = nullptr, evJoinCSR = nullptr, evJoinW = nullptr;
    if (sB == nullptr) {
        cudaStreamCreateWithFlags(&sB, cudaStreamNonBlocking);
        cudaEventCreateWithFlags(&evFork, cudaEventDisableTiming);
        cudaEventCreateWithFlags(&evJoinCSR, cudaEventDisableTiming);
        cudaEventCreateWithFlags(&evJoinW, cudaEventDisableTiming);
    }

    cudaFuncSetAttribute(mma_gemm_bias_kernel,
                         cudaFuncAttributeMaxDynamicSharedMemorySize, GEMM_SMEM_BYTES);
    cudaFuncSetAttribute(sem_mma_kernel,
                         cudaFuncAttributeMaxDynamicSharedMemorySize, GEMM_SMEM_BYTES);

    // ---- fork: weight splits + CSR build on stream B (input-only deps) ------
    cudaEventRecord(evFork, 0);
    cudaStreamWaitEvent(sB, evFork, 0);

    split_kernel<<<dim3(FOUT * K_IN / 4 / 256, 2), 256, 0, sB>>>(
        W_add, wh0, wm0, W_del, wh1, wm1, FOUT * K_IN / 4);
    cudaEventRecord(evJoinW, sB);

    dim3 ew_grid((E_EDGES + 255) / 256, 2);
    cudaMemsetAsync(deg0, 0, (size_t)N_NODES * sizeof(int), sB);
    cudaMemsetAsync(deg1, 0, (size_t)N_NODES * sizeof(int), sB);
    deg_kernel<<<ew_grid, 256, 0, sB>>>(ei_ad, deg0, ei_dd, deg1, E_EDGES);
    scan_kernel<<<2, 1024, 0, sB>>>(deg0, start0, cur0, deg1, start1, cur1);
    fill_kernel<<<ew_grid, 256, 0, sB>>>(ei_ad, cur0, csr0, ei_dd, cur1, csr1, E_EDGES);
    split_kernel<<<dim3(FOUT * FOUT / 4 / 256, 1), 256, 0, sB>>>(
        k_W, kwh, kwm, k_W, kwh, kwm, FOUT * FOUT / 4);
    cudaEventRecord(evJoinCSR, sB);

    // ---- main stream ---------------------------------------------------------
    cudaMemsetAsync(sad,   0, (size_t)N_NODES * 2 * sizeof(float), 0);
    cudaMemsetAsync(sdd,   0, (size_t)N_NODES * 2 * sizeof(float), 0);
    cudaMemsetAsync(score, 0, 2 * sizeof(float), 0);

    cudaStreamWaitEvent(0, evJoinW, 0);   // proj GEMM needs split weights

    dim3 gemm_grid(2, (N_NODES + 127) / 128, 2);     // (2, 157, 2) = 628 blocks
    mma_gemm_bias_kernel<<<gemm_grid, 256, GEMM_SMEM_BYTES>>>(
        x_add, wh0, wm0, b_add, ha,
        x_del, wh1, wm1, b_del, hd, N_NODES, K_IN);

    dots_kernel<<<N_NODES / 8, 256>>>(ha, hd, att_ad_s, att_ad_d, att_dd_s, att_dd_d,
                                      asad, adad, asdd, addd, N_NODES);

    edge_w_kernel<<<ew_grid, 256>>>(ei_ad, asad, adad, wad, sad,
                                    ei_dd, asdd, addd, wdd, sdd, E_EDGES);

    // ---- join: gather needs CSR (stream B) + weights (stream 0) -------------
    cudaStreamWaitEvent(0, evJoinCSR, 0);

    dim3 ga_grid((N_NODES + 7) / 8, 2);
    gather_kernel<<<ga_grid, 256>>>(
        ei_ad, csr0, start0, cur0, wad, sad, ha, oad,
        ei_dd, csr1, start1, cur1, wdd, sdd, hd, odd, N_NODES);

    dim3 sem_grid(2, (N_NODES + 127) / 128, 2);
    sem_mma_kernel<<<sem_grid, 256, GEMM_SMEM_BYTES>>>(
        oad, odd, kwh, kwm, k_b, q, score, N_NODES);

    final_kernel<<<(N_SEL * 64) / 256, 256>>>(del_idx, oad, odd, score, (float*)d_out);
}